// round 2
// baseline (speedup 1.0000x reference)
#include <cuda_runtime.h>

#define N 4096
#define C 64

// ---------------- scratch (device globals; no allocation) ----------------
__device__ float g_E[(size_t)4 * N * N];     // exp(logits) for 4 matrices (256MB)
__device__ float g_Qt[2][N * C];             // Q^T, pre-scaled by 1/8   [n][c]
__device__ float g_Kt[2][N * C];             // K^T                      [n][c]
__device__ float g_V[2][C * N];              // V                        [c][n]
__device__ float g_Vs[4][C * N];             // V / rowsum per matrix    [c][m]
__device__ float g_Prow[4][32][N];           // per-colblock rowsum partials
__device__ float g_rs[4][N];                 // reciprocal row sums
__device__ float g_Sp[2][4][C * N];          // message-passing partials (pair, msplit)
__device__ float g_Y[2][C * N];              // post-projection
__device__ float g_bn[2][2][C];              // {mean, rstd} per pair/channel

// ---------------- K1: QKV projections ----------------
__global__ void __launch_bounds__(256) qkv_kernel(
    const float* __restrict__ Xi, const float* __restrict__ Xj,
    const float* __restrict__ Wq, const float* __restrict__ Wk,
    const float* __restrict__ Wv) {
  __shared__ float Xs[C][128];
  int side = blockIdx.y;
  const float* X = side ? Xj : Xi;
  int n0 = blockIdx.x * 128;
  int t = threadIdx.x;
  for (int i = t; i < C * 32; i += 256) {
    int c = i >> 5, q = i & 31;
    *(float4*)&Xs[c][q * 4] = *(const float4*)&X[c * N + n0 + q * 4];
  }
  __syncthreads();
  int o = t & 63, g = t >> 6;  // o: out channel, g: n-phase (0..3)
  float acc[32];

  // --- Wq ---
  {
#pragma unroll
    for (int k = 0; k < 32; k++) acc[k] = 0.f;
    for (int c = 0; c < C; c++) {
      float w = __ldg(&Wq[o * C + c]);
#pragma unroll
      for (int k = 0; k < 32; k++) acc[k] = fmaf(w, Xs[c][g + 4 * k], acc[k]);
    }
#pragma unroll
    for (int k = 0; k < 32; k++)
      g_Qt[side][(n0 + g + 4 * k) * C + o] = acc[k] * 0.125f;  // / sqrt(C)
  }
  // --- Wk ---
  {
#pragma unroll
    for (int k = 0; k < 32; k++) acc[k] = 0.f;
    for (int c = 0; c < C; c++) {
      float w = __ldg(&Wk[o * C + c]);
#pragma unroll
      for (int k = 0; k < 32; k++) acc[k] = fmaf(w, Xs[c][g + 4 * k], acc[k]);
    }
#pragma unroll
    for (int k = 0; k < 32; k++) g_Kt[side][(n0 + g + 4 * k) * C + o] = acc[k];
  }
  // --- Wv ---
  {
#pragma unroll
    for (int k = 0; k < 32; k++) acc[k] = 0.f;
    for (int c = 0; c < C; c++) {
      float w = __ldg(&Wv[o * C + c]);
#pragma unroll
      for (int k = 0; k < 32; k++) acc[k] = fmaf(w, Xs[c][g + 4 * k], acc[k]);
    }
#pragma unroll
    for (int k = 0; k < 32; k++) g_V[side][o * N + n0 + g + 4 * k] = acc[k];
  }
}

// ---------------- K2: logits GEMM + exp + row-sum partials ----------------
// mat 0: (Qi,Ki)  mat 1: (Qi,Kj)  mat 2: (Qj,Kj)  mat 3: (Qj,Ki)
__global__ void __launch_bounds__(256) gemm_exp_kernel() {
  __shared__ float Qsm[32][132];  // k-major
  __shared__ float Ksm[32][132];
  int mat = blockIdx.z;
  int qs = mat >> 1;
  int ks = (mat == 1 || mat == 2) ? 1 : 0;
  const float* Qt = g_Qt[qs];
  const float* Kt = g_Kt[ks];
  int m0 = blockIdx.y * 128, n0 = blockIdx.x * 128;
  int t = threadIdx.x;
  int tx = t & 15, ty = t >> 4;

  float acc[8][8];
#pragma unroll
  for (int i = 0; i < 8; i++)
#pragma unroll
    for (int j = 0; j < 8; j++) acc[i][j] = 0.f;

  for (int kc = 0; kc < 2; kc++) {
    __syncthreads();
    for (int i = t; i < 1024; i += 256) {  // 128 rows x 8 float4
      int r = i >> 3, kq = i & 7;
      float4 v = *(const float4*)&Qt[(m0 + r) * C + kc * 32 + kq * 4];
      Qsm[kq * 4 + 0][r] = v.x; Qsm[kq * 4 + 1][r] = v.y;
      Qsm[kq * 4 + 2][r] = v.z; Qsm[kq * 4 + 3][r] = v.w;
      float4 u = *(const float4*)&Kt[(n0 + r) * C + kc * 32 + kq * 4];
      Ksm[kq * 4 + 0][r] = u.x; Ksm[kq * 4 + 1][r] = u.y;
      Ksm[kq * 4 + 2][r] = u.z; Ksm[kq * 4 + 3][r] = u.w;
    }
    __syncthreads();
#pragma unroll 8
    for (int k = 0; k < 32; k++) {
      float4 a0 = *(float4*)&Qsm[k][ty * 4];
      float4 a1 = *(float4*)&Qsm[k][64 + ty * 4];
      float4 b0 = *(float4*)&Ksm[k][tx * 4];
      float4 b1 = *(float4*)&Ksm[k][64 + tx * 4];
      float a[8] = {a0.x, a0.y, a0.z, a0.w, a1.x, a1.y, a1.z, a1.w};
      float b[8] = {b0.x, b0.y, b0.z, b0.w, b1.x, b1.y, b1.z, b1.w};
#pragma unroll
      for (int i = 0; i < 8; i++)
#pragma unroll
        for (int j = 0; j < 8; j++) acc[i][j] = fmaf(a[i], b[j], acc[i][j]);
    }
  }

  float* E = &g_E[(size_t)mat * N * N];
  float rp[8];
#pragma unroll
  for (int i = 0; i < 8; i++) {
    int row = (i < 4) ? (ty * 4 + i) : (64 + ty * 4 + (i - 4));
    float4 e0, e1;
    e0.x = __expf(acc[i][0]); e0.y = __expf(acc[i][1]);
    e0.z = __expf(acc[i][2]); e0.w = __expf(acc[i][3]);
    e1.x = __expf(acc[i][4]); e1.y = __expf(acc[i][5]);
    e1.z = __expf(acc[i][6]); e1.w = __expf(acc[i][7]);
    *(float4*)&E[(size_t)(m0 + row) * N + n0 + tx * 4] = e0;
    *(float4*)&E[(size_t)(m0 + row) * N + n0 + 64 + tx * 4] = e1;
    rp[i] = ((e0.x + e0.y) + (e0.z + e0.w)) + ((e1.x + e1.y) + (e1.z + e1.w));
  }
  // reduce row partials over the 16 tx lanes (xor 1..8 stays within tx group)
#pragma unroll
  for (int i = 0; i < 8; i++) {
    float v = rp[i];
    v += __shfl_xor_sync(0xffffffffu, v, 1);
    v += __shfl_xor_sync(0xffffffffu, v, 2);
    v += __shfl_xor_sync(0xffffffffu, v, 4);
    v += __shfl_xor_sync(0xffffffffu, v, 8);
    if (tx == 0) {
      int row = (i < 4) ? (ty * 4 + i) : (64 + ty * 4 + (i - 4));
      g_Prow[mat][blockIdx.x][m0 + row] = v;
    }
  }
}

// ---------------- K3a: reduce row-sum partials -> reciprocal ----------------
__global__ void rowsum_kernel() {
  int id = blockIdx.x * 256 + threadIdx.x;  // 4*4096
  int mat = id >> 12, m = id & 4095;
  float s = 0.f;
#pragma unroll
  for (int b = 0; b < 32; b++) s += g_Prow[mat][b][m];
  g_rs[mat][m] = 1.0f / s;
}

// ---------------- K3b: scale V by reciprocal row sums ----------------
__global__ void vscale_kernel() {
  int id = blockIdx.x * 256 + threadIdx.x;  // 4 * 64 * 4096
  int mat = id >> 18;
  int rem = id & 262143;
  int m = rem & 4095;
  g_Vs[mat][rem] = g_V[mat >> 1][rem] * g_rs[mat][m];
}

// ---------------- K4: message passing  S = Vs_a*E_a + Vs_b*E_b ----------------
__global__ void __launch_bounds__(256) mp_kernel() {
  __shared__ float E1s[16][132], E2s[16][132];
  __shared__ float V1s[16][68], V2s[16][68];
  int n0 = blockIdx.x * 128;
  int msplit = blockIdx.y;  // 0..3
  int pair = blockIdx.z;
  int matA = 2 * pair, matB = 2 * pair + 1;
  const float* E1 = &g_E[(size_t)matA * N * N];
  const float* E2 = &g_E[(size_t)matB * N * N];
  const float* VA = g_Vs[matA];
  const float* VB = g_Vs[matB];
  int t = threadIdx.x, tx = t & 15, ty = t >> 4;

  float acc[4][8];
#pragma unroll
  for (int i = 0; i < 4; i++)
#pragma unroll
    for (int j = 0; j < 8; j++) acc[i][j] = 0.f;

  int mbase = msplit * 1024;
  for (int mc = 0; mc < 1024; mc += 16) {
    __syncthreads();
    for (int i = t; i < 1024; i += 256) {  // 16 m x 64 c
      int mm = i & 15, c = i >> 4;
      V1s[mm][c] = VA[c * N + mbase + mc + mm];
      V2s[mm][c] = VB[c * N + mbase + mc + mm];
    }
    for (int i = t; i < 512; i += 256) {  // 16 rows x 32 float4
      int r = i >> 5, q = i & 31;
      *(float4*)&E1s[r][q * 4] = *(const float4*)&E1[(size_t)(mbase + mc + r) * N + n0 + q * 4];
      *(float4*)&E2s[r][q * 4] = *(const float4*)&E2[(size_t)(mbase + mc + r) * N + n0 + q * 4];
    }
    __syncthreads();
#pragma unroll
    for (int mm = 0; mm < 16; mm++) {
      float4 a1 = *(float4*)&V1s[mm][ty * 4];
      float4 a2 = *(float4*)&V2s[mm][ty * 4];
      float4 b10 = *(float4*)&E1s[mm][tx * 4];
      float4 b11 = *(float4*)&E1s[mm][64 + tx * 4];
      float4 b20 = *(float4*)&E2s[mm][tx * 4];
      float4 b21 = *(float4*)&E2s[mm][64 + tx * 4];
      float aa1[4] = {a1.x, a1.y, a1.z, a1.w};
      float aa2[4] = {a2.x, a2.y, a2.z, a2.w};
      float bb1[8] = {b10.x, b10.y, b10.z, b10.w, b11.x, b11.y, b11.z, b11.w};
      float bb2[8] = {b20.x, b20.y, b20.z, b20.w, b21.x, b21.y, b21.z, b21.w};
#pragma unroll
      for (int i = 0; i < 4; i++)
#pragma unroll
        for (int j = 0; j < 8; j++) {
          acc[i][j] = fmaf(aa1[i], bb1[j], acc[i][j]);
          acc[i][j] = fmaf(aa2[i], bb2[j], acc[i][j]);
        }
    }
  }
  float* Sp = g_Sp[pair][msplit];
#pragma unroll
  for (int i = 0; i < 4; i++) {
    int c = ty * 4 + i;
    float4 w0 = {acc[i][0], acc[i][1], acc[i][2], acc[i][3]};
    float4 w1 = {acc[i][4], acc[i][5], acc[i][6], acc[i][7]};
    *(float4*)&Sp[c * N + n0 + tx * 4] = w0;
    *(float4*)&Sp[c * N + n0 + 64 + tx * 4] = w1;
  }
}

// ---------------- K5: Y = Wp * (S + X) ----------------
__global__ void __launch_bounds__(256) ygemm_kernel(
    const float* __restrict__ Xi, const float* __restrict__ Xj,
    const float* __restrict__ Wpi, const float* __restrict__ Wpj) {
  __shared__ float Ts[C][128];
  __shared__ float Wsm[C][C];
  int pair = blockIdx.y;
  const float* X = pair ? Xj : Xi;
  const float* Wp = pair ? Wpj : Wpi;
  int n0 = blockIdx.x * 128;
  int t = threadIdx.x;
  for (int i = t; i < C * C / 4; i += 256)
    *(float4*)&Wsm[0][i * 4] = *(const float4*)&Wp[i * 4];
  for (int i = t; i < C * 32; i += 256) {
    int c = i >> 5, q = i & 31;
    float4 v = *(const float4*)&X[c * N + n0 + q * 4];
#pragma unroll
    for (int s = 0; s < 4; s++) {
      float4 p = *(const float4*)&g_Sp[pair][s][c * N + n0 + q * 4];
      v.x += p.x; v.y += p.y; v.z += p.z; v.w += p.w;
    }
    *(float4*)&Ts[c][q * 4] = v;
  }
  __syncthreads();
  int n = t & 127, h = t >> 7;  // h: 0/1 -> output channels h*32..h*32+31
  float acc[32];
#pragma unroll
  for (int oo = 0; oo < 32; oo++) acc[oo] = 0.f;
  for (int c = 0; c < C; c++) {
    float x = Ts[c][n];
#pragma unroll
    for (int oo = 0; oo < 32; oo++)
      acc[oo] = fmaf(Wsm[h * 32 + oo][c], x, acc[oo]);
  }
#pragma unroll
  for (int oo = 0; oo < 32; oo++)
    g_Y[pair][(h * 32 + oo) * N + n0 + n] = acc[oo];
}

// ---------------- K6: BN stats (one block per pair/channel) ----------------
__global__ void bnstats_kernel() {
  int pair = blockIdx.x >> 6, c = blockIdx.x & 63;
  const float* y = &g_Y[pair][c * N];
  float s = 0.f, sq = 0.f;
  for (int n = threadIdx.x; n < N; n += 128) {
    float v = y[n];
    s += v;
    sq += v * v;
  }
  __shared__ float rs_[128], rq_[128];
  rs_[threadIdx.x] = s; rq_[threadIdx.x] = sq;
  __syncthreads();
  for (int off = 64; off > 0; off >>= 1) {
    if (threadIdx.x < off) {
      rs_[threadIdx.x] += rs_[threadIdx.x + off];
      rq_[threadIdx.x] += rq_[threadIdx.x + off];
    }
    __syncthreads();
  }
  if (threadIdx.x == 0) {
    float mean = rs_[0] * (1.0f / N);
    float var = rq_[0] * (1.0f / N) - mean * mean;
    g_bn[pair][0][c] = mean;
    g_bn[pair][1][c] = rsqrtf(var + 1e-5f);
  }
}

// ---------------- K7: BN + LeakyReLU + sum ----------------
__global__ void epilogue_kernel(const float* __restrict__ gi, const float* __restrict__ bi,
                                const float* __restrict__ gj, const float* __restrict__ bj,
                                float* __restrict__ out) {
  int id = blockIdx.x * 256 + threadIdx.x;  // 64 * 4096
  int c = id >> 12;
  float yi = g_Y[0][id], yj = g_Y[1][id];
  float vi = (yi - g_bn[0][0][c]) * g_bn[0][1][c] * gi[c] + bi[c];
  float vj = (yj - g_bn[1][0][c]) * g_bn[1][1][c] * gj[c] + bj[c];
  vi = (vi >= 0.f) ? vi : 0.01f * vi;
  vj = (vj >= 0.f) ? vj : 0.01f * vj;
  out[id] = vi + vj;
}

// ---------------- launch ----------------
extern "C" void kernel_launch(void* const* d_in, const int* in_sizes, int n_in,
                              void* d_out, int out_size) {
  const float* Xi = (const float*)d_in[0];
  const float* Xj = (const float*)d_in[1];
  const float* Wq = (const float*)d_in[2];
  const float* Wk = (const float*)d_in[3];
  const float* Wv = (const float*)d_in[4];
  const float* Wpi = (const float*)d_in[5];
  const float* Wpj = (const float*)d_in[6];
  const float* gi = (const float*)d_in[7];
  const float* bi = (const float*)d_in[8];
  const float* gj = (const float*)d_in[9];
  const float* bj = (const float*)d_in[10];
  float* out = (float*)d_out;

  qkv_kernel<<<dim3(32, 2), 256>>>(Xi, Xj, Wq, Wk, Wv);
  gemm_exp_kernel<<<dim3(32, 32, 4), 256>>>();
  rowsum_kernel<<<64, 256>>>();
  vscale_kernel<<<4096, 256>>>();
  mp_kernel<<<dim3(32, 4, 2), 256>>>();
  ygemm_kernel<<<dim3(32, 2), 256>>>(Xi, Xj, Wpi, Wpj);
  bnstats_kernel<<<128, 128>>>();
  epilogue_kernel<<<1024, 256>>>(gi, bi, gj, bj, out);
}